// round 7
// baseline (speedup 1.0000x reference)
#include <cuda_runtime.h>
#include <cuda_bf16.h>
#include <stdint.h>

// Problem constants (fixed by the dataset)
#define NMAX 100000
#define EMAX 1600000
#define DIN  256
#define DOUT 128

// ---------------- scratch (static device allocations; no runtime alloc) ----
static __device__ int    d_deg[NMAX];
static __device__ float  d_dinv[NMAX];
static __device__ int    d_rowstart[NMAX];
static __device__ int    d_cursor[NMAX];
static __device__ int    d_csr[EMAX];
static __device__ float4 d_g4[(size_t)NMAX * DOUT / 4];   // 51.2 MB, 16B-aligned
static __device__ int    d_tmpscan[NMAX];
static __device__ int    d_bsum[512];
static __device__ int    d_bsumscan[512];
static __device__ int    d_is64;   // 1 if edge_index delivered as int64, 0 if int32

// ---------------- dtype probe (parallel, graph-capturable) -----------------
// Interpret first 256 8-byte words as int64 node indices. True int64 data is
// always in [0, NMAX). Packed-int32 data gives lo + hi*2^32 >= 2^32 unless
// hi (a node index) happens to be 0 (p ~ 1e-5 per word).
__global__ void k_detect(const long long* __restrict__ p) {
    __shared__ int anybad;
    int t = threadIdx.x;
    if (t == 0) anybad = 0;
    __syncthreads();
    long long v = p[t];
    int bad = (v < 0 || v >= NMAX) ? 1 : 0;
    unsigned m = __ballot_sync(0xffffffffu, bad);
    if ((t & 31) == 0 && m) atomicOr(&anybad, 1);
    __syncthreads();
    if (t == 0) d_is64 = anybad ? 0 : 1;
}

__device__ __forceinline__ int load_idx(const void* __restrict__ ei,
                                        size_t pos) {
    if (d_is64) return (int)((const long long*)ei)[pos];
    return ((const int*)ei)[pos];
}

// ---------------- small kernels -------------------------------------------
__global__ void k_init(int n) {
    int i = blockIdx.x * blockDim.x + threadIdx.x;
    if (i < n) d_deg[i] = 0;
}

__global__ void k_degree(const void* __restrict__ ei, int e) {
    int i = blockIdx.x * blockDim.x + threadIdx.x;
    if (i < e) {
        int d = load_idx(ei, (size_t)e + i);   // dst row
        atomicAdd(&d_deg[d], 1);
    }
}

__global__ void k_dinv(int n) {
    int i = blockIdx.x * blockDim.x + threadIdx.x;
    if (i < n) d_dinv[i] = rsqrtf((float)(d_deg[i] + 1));  // +1 = self-loop
}

// Inclusive block scan of deg, 512 elems/block
__global__ void k_scan1(int n) {
    __shared__ int s[512];
    int t = threadIdx.x;
    int i = blockIdx.x * 512 + t;
    s[t] = (i < n) ? d_deg[i] : 0;
    __syncthreads();
    #pragma unroll
    for (int off = 1; off < 512; off <<= 1) {
        int add = (t >= off) ? s[t - off] : 0;
        __syncthreads();
        s[t] += add;
        __syncthreads();
    }
    if (i < n) d_tmpscan[i] = s[t];
    if (t == 511) d_bsum[blockIdx.x] = s[511];
}

// Single-block inclusive scan of the block sums (nb <= 256)
__global__ void k_scan2(int nb) {
    __shared__ int s[256];
    int t = threadIdx.x;
    s[t] = (t < nb) ? d_bsum[t] : 0;
    __syncthreads();
    #pragma unroll
    for (int off = 1; off < 256; off <<= 1) {
        int add = (t >= off) ? s[t - off] : 0;
        __syncthreads();
        s[t] += add;
        __syncthreads();
    }
    if (t < nb) d_bsumscan[t] = s[t];
}

__global__ void k_scan3(int n) {
    int i = blockIdx.x * blockDim.x + threadIdx.x;
    if (i < n) {
        int b = i >> 9;
        int base = b ? d_bsumscan[b - 1] : 0;
        int rs = base + d_tmpscan[i] - d_deg[i];  // exclusive
        d_rowstart[i] = rs;
        d_cursor[i] = rs;
    }
}

__global__ void k_fill(const void* __restrict__ ei, int e) {
    int i = blockIdx.x * blockDim.x + threadIdx.x;
    if (i < e) {
        int s = load_idx(ei, (size_t)i);            // src
        int d = load_idx(ei, (size_t)e + i);        // dst
        int p = atomicAdd(&d_cursor[d], 1);
        d_csr[p] = s;
    }
}

// ---------------- GEMM: g[r,:] = dinv[r] * (x[r,:] @ W) -------------------
// BM=64, BN=128, BK=32, 256 threads, 8x4 register tile per thread.
// Accumulators paired along M in f32x2 so A-pairs come free from LDS.128;
// only B scalars need a 1-MOV dup per k-step. FMA-pipe work halves vs FFMA.
__global__ __launch_bounds__(256) void k_gemm(const float* __restrict__ x,
                                              const float* __restrict__ W,
                                              int n) {
    __shared__ __align__(16) float As[32][68];  // [k][row], 16B-aligned rows
    __shared__ __align__(16) float Bs[32][128]; // [k][col]

    const int tid = threadIdx.x;
    const int tx = tid & 31;        // col group: cols tx*4 .. tx*4+3
    const int ty = tid >> 5;        // row group: rows ty*8 .. ty*8+7
    const int row0 = blockIdx.x * 64;

    // acc2[i2][j] = {row 2*i2, row 2*i2+1} at column tx*4+j (packed f32x2)
    unsigned long long acc2[4][4];
    #pragma unroll
    for (int i = 0; i < 4; i++)
        #pragma unroll
        for (int j = 0; j < 4; j++) acc2[i][j] = 0ull;

    for (int kt = 0; kt < DIN; kt += 32) {
        // load A tile (64 rows x 32 k), transposed into As[k][row]
        #pragma unroll
        for (int j = 0; j < 2; j++) {
            int idx = tid + j * 256;         // 0..511 float4 slots
            int r = idx >> 3;
            int kk = (idx & 7) * 4;
            float4 v = make_float4(0.f, 0.f, 0.f, 0.f);
            int grow = row0 + r;
            if (grow < n)
                v = *(const float4*)(x + (size_t)grow * DIN + kt + kk);
            As[kk + 0][r] = v.x;
            As[kk + 1][r] = v.y;
            As[kk + 2][r] = v.z;
            As[kk + 3][r] = v.w;
        }
        // load B tile (32 k x 128 cols)
        #pragma unroll
        for (int j = 0; j < 4; j++) {
            int idx = tid + j * 256;         // 0..1023 float4 slots
            int kr = idx >> 5;
            int c = (idx & 31) * 4;
            *(float4*)&Bs[kr][c] = *(const float4*)(W + (size_t)(kt + kr) * DOUT + c);
        }
        __syncthreads();

        #pragma unroll
        for (int k = 0; k < 32; k++) {
            float4 a0 = *(const float4*)&As[k][ty * 8];     // rows +0..3
            float4 a1 = *(const float4*)&As[k][ty * 8 + 4]; // rows +4..7
            float4 bf = *(const float4*)&Bs[k][tx * 4];

            // A pairs along M (consecutive regs from LDS.128 -> free pack)
            unsigned long long ap[4];
            asm("mov.b64 %0, {%1, %2};" : "=l"(ap[0]) : "f"(a0.x), "f"(a0.y));
            asm("mov.b64 %0, {%1, %2};" : "=l"(ap[1]) : "f"(a0.z), "f"(a0.w));
            asm("mov.b64 %0, {%1, %2};" : "=l"(ap[2]) : "f"(a1.x), "f"(a1.y));
            asm("mov.b64 %0, {%1, %2};" : "=l"(ap[3]) : "f"(a1.z), "f"(a1.w));
            // B scalars duplicated into both halves (1 MOV each)
            unsigned long long bd[4];
            asm("mov.b64 %0, {%1, %1};" : "=l"(bd[0]) : "f"(bf.x));
            asm("mov.b64 %0, {%1, %1};" : "=l"(bd[1]) : "f"(bf.y));
            asm("mov.b64 %0, {%1, %1};" : "=l"(bd[2]) : "f"(bf.z));
            asm("mov.b64 %0, {%1, %1};" : "=l"(bd[3]) : "f"(bf.w));

            #pragma unroll
            for (int i = 0; i < 4; i++)
                #pragma unroll
                for (int j = 0; j < 4; j++)
                    asm("fma.rn.f32x2 %0, %1, %2, %0;"
                        : "+l"(acc2[i][j]) : "l"(ap[i]), "l"(bd[j]));
        }
        __syncthreads();
    }

    #pragma unroll
    for (int i2 = 0; i2 < 4; i2++) {
        float lo[4], hi[4];
        #pragma unroll
        for (int j = 0; j < 4; j++)
            asm("mov.b64 {%0, %1}, %2;"
                : "=f"(lo[j]), "=f"(hi[j]) : "l"(acc2[i2][j]));
        int r0 = row0 + ty * 8 + i2 * 2;
        if (r0 < n) {
            float dv = d_dinv[r0];
            d_g4[(size_t)r0 * 32 + tx] =
                make_float4(lo[0] * dv, lo[1] * dv, lo[2] * dv, lo[3] * dv);
        }
        int r1 = r0 + 1;
        if (r1 < n) {
            float dv = d_dinv[r1];
            d_g4[(size_t)r1 * 32 + tx] =
                make_float4(hi[0] * dv, hi[1] * dv, hi[2] * dv, hi[3] * dv);
        }
    }
}

// ---------------- Aggregate: out[d] = relu(dinv[d]*(g[d] + sum g[src]) + b)
// One warp per node; lane owns float4 column group `lane`.
__global__ __launch_bounds__(256) void k_agg(const float* __restrict__ bias,
                                             float* __restrict__ out, int n) {
    int gwarp = (blockIdx.x * blockDim.x + threadIdx.x) >> 5;
    int lane = threadIdx.x & 31;
    if (gwarp >= n) return;

    float4 acc = d_g4[(size_t)gwarp * 32 + lane];   // self-loop term

    int start = d_rowstart[gwarp];
    int cnt = d_deg[gwarp];
    int e = start, end = start + cnt;

    for (; e + 4 <= end; e += 4) {
        int s0 = d_csr[e + 0];
        int s1 = d_csr[e + 1];
        int s2 = d_csr[e + 2];
        int s3 = d_csr[e + 3];
        float4 v0 = d_g4[(size_t)s0 * 32 + lane];
        float4 v1 = d_g4[(size_t)s1 * 32 + lane];
        float4 v2 = d_g4[(size_t)s2 * 32 + lane];
        float4 v3 = d_g4[(size_t)s3 * 32 + lane];
        acc.x += (v0.x + v1.x) + (v2.x + v3.x);
        acc.y += (v0.y + v1.y) + (v2.y + v3.y);
        acc.z += (v0.z + v1.z) + (v2.z + v3.z);
        acc.w += (v0.w + v1.w) + (v2.w + v3.w);
    }
    for (; e < end; e++) {
        int s = d_csr[e];
        float4 v = d_g4[(size_t)s * 32 + lane];
        acc.x += v.x; acc.y += v.y; acc.z += v.z; acc.w += v.w;
    }

    float dv = d_dinv[gwarp];
    float4 bv = ((const float4*)bias)[lane];
    float4 o;
    o.x = fmaxf(fmaf(dv, acc.x, bv.x), 0.f);
    o.y = fmaxf(fmaf(dv, acc.y, bv.y), 0.f);
    o.z = fmaxf(fmaf(dv, acc.z, bv.z), 0.f);
    o.w = fmaxf(fmaf(dv, acc.w, bv.w), 0.f);
    ((float4*)out)[(size_t)gwarp * 32 + lane] = o;
}

// ---------------- launch ---------------------------------------------------
extern "C" void kernel_launch(void* const* d_in, const int* in_sizes, int n_in,
                              void* d_out, int out_size) {
    const float* x = (const float*)d_in[0];
    const void*  ei = (const void*)d_in[1];
    const float* W = (const float*)d_in[2];
    const float* bias = (const float*)d_in[3];
    float* out = (float*)d_out;

    int n = in_sizes[0] / DIN;    // 100000
    int e = in_sizes[1] / 2;      // 1600000 (element count is 2*E either dtype)
    int nb1 = (n + 511) / 512;    // 196 block sums (<= 256)

    k_detect<<<1, 256>>>((const long long*)ei);
    k_init<<<(n + 255) / 256, 256>>>(n);
    k_degree<<<(e + 255) / 256, 256>>>(ei, e);
    k_dinv<<<(n + 255) / 256, 256>>>(n);
    k_scan1<<<nb1, 512>>>(n);
    k_scan2<<<1, 256>>>(nb1);
    k_scan3<<<(n + 255) / 256, 256>>>(n);
    k_fill<<<(e + 255) / 256, 256>>>(ei, e);
    k_gemm<<<(n + 63) / 64, 256>>>(x, W, n);
    k_agg<<<(n + 7) / 8, 256>>>(bias, out, n);
}

// round 8
// speedup vs baseline: 1.0001x; 1.0001x over previous
#include <cuda_runtime.h>
#include <cuda_bf16.h>
#include <stdint.h>

// Problem constants (fixed by the dataset)
#define NMAX 100000
#define EMAX 1600000
#define DIN  256
#define DOUT 128

// ---------------- scratch (static device allocations; no runtime alloc) ----
static __device__ int    d_deg[NMAX];
static __device__ float  d_dinv[NMAX];
static __device__ int    d_rowstart[NMAX];
static __device__ int    d_cursor[NMAX];
static __device__ int    d_csr[EMAX];
static __device__ float4 d_g4[(size_t)NMAX * DOUT / 4];   // 51.2 MB, 16B-aligned
static __device__ int    d_tmpscan[NMAX];
static __device__ int    d_bsum[512];
static __device__ int    d_bsumscan[512];
static __device__ int    d_is64;   // 1 if edge_index delivered as int64, 0 if int32

// ---------------- dtype probe (parallel, graph-capturable) -----------------
// Interpret first 256 8-byte words as int64 node indices. True int64 data is
// always in [0, NMAX). Packed-int32 data gives lo + hi*2^32 >= 2^32 unless
// hi (a node index) happens to be 0 (p ~ 1e-5 per word).
__global__ void k_detect(const long long* __restrict__ p) {
    __shared__ int anybad;
    int t = threadIdx.x;
    if (t == 0) anybad = 0;
    __syncthreads();
    long long v = p[t];
    int bad = (v < 0 || v >= NMAX) ? 1 : 0;
    unsigned m = __ballot_sync(0xffffffffu, bad);
    if ((t & 31) == 0 && m) atomicOr(&anybad, 1);
    __syncthreads();
    if (t == 0) d_is64 = anybad ? 0 : 1;
}

__device__ __forceinline__ int load_idx(const void* __restrict__ ei,
                                        size_t pos) {
    if (d_is64) return (int)((const long long*)ei)[pos];
    return ((const int*)ei)[pos];
}

// ---------------- small kernels -------------------------------------------
__global__ void k_init(int n) {
    int i = blockIdx.x * blockDim.x + threadIdx.x;
    if (i < n) d_deg[i] = 0;
}

__global__ void k_degree(const void* __restrict__ ei, int e) {
    int i = blockIdx.x * blockDim.x + threadIdx.x;
    if (i < e) {
        int d = load_idx(ei, (size_t)e + i);   // dst row
        atomicAdd(&d_deg[d], 1);
    }
}

__global__ void k_dinv(int n) {
    int i = blockIdx.x * blockDim.x + threadIdx.x;
    if (i < n) d_dinv[i] = rsqrtf((float)(d_deg[i] + 1));  // +1 = self-loop
}

// Inclusive block scan of deg, 512 elems/block
__global__ void k_scan1(int n) {
    __shared__ int s[512];
    int t = threadIdx.x;
    int i = blockIdx.x * 512 + t;
    s[t] = (i < n) ? d_deg[i] : 0;
    __syncthreads();
    #pragma unroll
    for (int off = 1; off < 512; off <<= 1) {
        int add = (t >= off) ? s[t - off] : 0;
        __syncthreads();
        s[t] += add;
        __syncthreads();
    }
    if (i < n) d_tmpscan[i] = s[t];
    if (t == 511) d_bsum[blockIdx.x] = s[511];
}

// Single-block inclusive scan of the block sums (nb <= 256)
__global__ void k_scan2(int nb) {
    __shared__ int s[256];
    int t = threadIdx.x;
    s[t] = (t < nb) ? d_bsum[t] : 0;
    __syncthreads();
    #pragma unroll
    for (int off = 1; off < 256; off <<= 1) {
        int add = (t >= off) ? s[t - off] : 0;
        __syncthreads();
        s[t] += add;
        __syncthreads();
    }
    if (t < nb) d_bsumscan[t] = s[t];
}

__global__ void k_scan3(int n) {
    int i = blockIdx.x * blockDim.x + threadIdx.x;
    if (i < n) {
        int b = i >> 9;
        int base = b ? d_bsumscan[b - 1] : 0;
        int rs = base + d_tmpscan[i] - d_deg[i];  // exclusive
        d_rowstart[i] = rs;
        d_cursor[i] = rs;
    }
}

__global__ void k_fill(const void* __restrict__ ei, int e) {
    int i = blockIdx.x * blockDim.x + threadIdx.x;
    if (i < e) {
        int s = load_idx(ei, (size_t)i);            // src
        int d = load_idx(ei, (size_t)e + i);        // dst
        int p = atomicAdd(&d_cursor[d], 1);
        d_csr[p] = s;
    }
}

// ---------------- GEMM: g[r,:] = dinv[r] * (x[r,:] @ W) -------------------
// BM=64, BN=128, BK=32, 256 threads, 8x4 register tile per thread.
// Accumulators paired along M in f32x2 so A-pairs come free from LDS.128;
// only B scalars need a 1-MOV dup per k-step. FMA-pipe work halves vs FFMA.
__global__ __launch_bounds__(256) void k_gemm(const float* __restrict__ x,
                                              const float* __restrict__ W,
                                              int n) {
    __shared__ __align__(16) float As[32][68];  // [k][row], 16B-aligned rows
    __shared__ __align__(16) float Bs[32][128]; // [k][col]

    const int tid = threadIdx.x;
    const int tx = tid & 31;        // col group: cols tx*4 .. tx*4+3
    const int ty = tid >> 5;        // row group: rows ty*8 .. ty*8+7
    const int row0 = blockIdx.x * 64;

    // acc2[i2][j] = {row 2*i2, row 2*i2+1} at column tx*4+j (packed f32x2)
    unsigned long long acc2[4][4];
    #pragma unroll
    for (int i = 0; i < 4; i++)
        #pragma unroll
        for (int j = 0; j < 4; j++) acc2[i][j] = 0ull;

    for (int kt = 0; kt < DIN; kt += 32) {
        // load A tile (64 rows x 32 k), transposed into As[k][row]
        #pragma unroll
        for (int j = 0; j < 2; j++) {
            int idx = tid + j * 256;         // 0..511 float4 slots
            int r = idx >> 3;
            int kk = (idx & 7) * 4;
            float4 v = make_float4(0.f, 0.f, 0.f, 0.f);
            int grow = row0 + r;
            if (grow < n)
                v = *(const float4*)(x + (size_t)grow * DIN + kt + kk);
            As[kk + 0][r] = v.x;
            As[kk + 1][r] = v.y;
            As[kk + 2][r] = v.z;
            As[kk + 3][r] = v.w;
        }
        // load B tile (32 k x 128 cols)
        #pragma unroll
        for (int j = 0; j < 4; j++) {
            int idx = tid + j * 256;         // 0..1023 float4 slots
            int kr = idx >> 5;
            int c = (idx & 31) * 4;
            *(float4*)&Bs[kr][c] = *(const float4*)(W + (size_t)(kt + kr) * DOUT + c);
        }
        __syncthreads();

        #pragma unroll
        for (int k = 0; k < 32; k++) {
            float4 a0 = *(const float4*)&As[k][ty * 8];     // rows +0..3
            float4 a1 = *(const float4*)&As[k][ty * 8 + 4]; // rows +4..7
            float4 bf = *(const float4*)&Bs[k][tx * 4];

            // A pairs along M (consecutive regs from LDS.128 -> free pack)
            unsigned long long ap[4];
            asm("mov.b64 %0, {%1, %2};" : "=l"(ap[0]) : "f"(a0.x), "f"(a0.y));
            asm("mov.b64 %0, {%1, %2};" : "=l"(ap[1]) : "f"(a0.z), "f"(a0.w));
            asm("mov.b64 %0, {%1, %2};" : "=l"(ap[2]) : "f"(a1.x), "f"(a1.y));
            asm("mov.b64 %0, {%1, %2};" : "=l"(ap[3]) : "f"(a1.z), "f"(a1.w));
            // B scalars duplicated into both halves (1 MOV each)
            unsigned long long bd[4];
            asm("mov.b64 %0, {%1, %1};" : "=l"(bd[0]) : "f"(bf.x));
            asm("mov.b64 %0, {%1, %1};" : "=l"(bd[1]) : "f"(bf.y));
            asm("mov.b64 %0, {%1, %1};" : "=l"(bd[2]) : "f"(bf.z));
            asm("mov.b64 %0, {%1, %1};" : "=l"(bd[3]) : "f"(bf.w));

            #pragma unroll
            for (int i = 0; i < 4; i++)
                #pragma unroll
                for (int j = 0; j < 4; j++)
                    asm("fma.rn.f32x2 %0, %1, %2, %0;"
                        : "+l"(acc2[i][j]) : "l"(ap[i]), "l"(bd[j]));
        }
        __syncthreads();
    }

    #pragma unroll
    for (int i2 = 0; i2 < 4; i2++) {
        float lo[4], hi[4];
        #pragma unroll
        for (int j = 0; j < 4; j++)
            asm("mov.b64 {%0, %1}, %2;"
                : "=f"(lo[j]), "=f"(hi[j]) : "l"(acc2[i2][j]));
        int r0 = row0 + ty * 8 + i2 * 2;
        if (r0 < n) {
            float dv = d_dinv[r0];
            d_g4[(size_t)r0 * 32 + tx] =
                make_float4(lo[0] * dv, lo[1] * dv, lo[2] * dv, lo[3] * dv);
        }
        int r1 = r0 + 1;
        if (r1 < n) {
            float dv = d_dinv[r1];
            d_g4[(size_t)r1 * 32 + tx] =
                make_float4(hi[0] * dv, hi[1] * dv, hi[2] * dv, hi[3] * dv);
        }
    }
}

// ---------------- Aggregate: out[d] = relu(dinv[d]*(g[d] + sum g[src]) + b)
// One warp per node; lane owns float4 column group `lane`.
__global__ __launch_bounds__(256) void k_agg(const float* __restrict__ bias,
                                             float* __restrict__ out, int n) {
    int gwarp = (blockIdx.x * blockDim.x + threadIdx.x) >> 5;
    int lane = threadIdx.x & 31;
    if (gwarp >= n) return;

    float4 acc = d_g4[(size_t)gwarp * 32 + lane];   // self-loop term

    int start = d_rowstart[gwarp];
    int cnt = d_deg[gwarp];
    int e = start, end = start + cnt;

    for (; e + 4 <= end; e += 4) {
        int s0 = d_csr[e + 0];
        int s1 = d_csr[e + 1];
        int s2 = d_csr[e + 2];
        int s3 = d_csr[e + 3];
        float4 v0 = d_g4[(size_t)s0 * 32 + lane];
        float4 v1 = d_g4[(size_t)s1 * 32 + lane];
        float4 v2 = d_g4[(size_t)s2 * 32 + lane];
        float4 v3 = d_g4[(size_t)s3 * 32 + lane];
        acc.x += (v0.x + v1.x) + (v2.x + v3.x);
        acc.y += (v0.y + v1.y) + (v2.y + v3.y);
        acc.z += (v0.z + v1.z) + (v2.z + v3.z);
        acc.w += (v0.w + v1.w) + (v2.w + v3.w);
    }
    for (; e < end; e++) {
        int s = d_csr[e];
        float4 v = d_g4[(size_t)s * 32 + lane];
        acc.x += v.x; acc.y += v.y; acc.z += v.z; acc.w += v.w;
    }

    float dv = d_dinv[gwarp];
    float4 bv = ((const float4*)bias)[lane];
    float4 o;
    o.x = fmaxf(fmaf(dv, acc.x, bv.x), 0.f);
    o.y = fmaxf(fmaf(dv, acc.y, bv.y), 0.f);
    o.z = fmaxf(fmaf(dv, acc.z, bv.z), 0.f);
    o.w = fmaxf(fmaf(dv, acc.w, bv.w), 0.f);
    ((float4*)out)[(size_t)gwarp * 32 + lane] = o;
}

// ---------------- launch ---------------------------------------------------
extern "C" void kernel_launch(void* const* d_in, const int* in_sizes, int n_in,
                              void* d_out, int out_size) {
    const float* x = (const float*)d_in[0];
    const void*  ei = (const void*)d_in[1];
    const float* W = (const float*)d_in[2];
    const float* bias = (const float*)d_in[3];
    float* out = (float*)d_out;

    int n = in_sizes[0] / DIN;    // 100000
    int e = in_sizes[1] / 2;      // 1600000 (element count is 2*E either dtype)
    int nb1 = (n + 511) / 512;    // 196 block sums (<= 256)

    k_detect<<<1, 256>>>((const long long*)ei);
    k_init<<<(n + 255) / 256, 256>>>(n);
    k_degree<<<(e + 255) / 256, 256>>>(ei, e);
    k_dinv<<<(n + 255) / 256, 256>>>(n);
    k_scan1<<<nb1, 512>>>(n);
    k_scan2<<<1, 256>>>(nb1);
    k_scan3<<<(n + 255) / 256, 256>>>(n);
    k_fill<<<(e + 255) / 256, 256>>>(ei, e);
    k_gemm<<<(n + 63) / 64, 256>>>(x, W, n);
    k_agg<<<(n + 7) / 8, 256>>>(bias, out, n);
}

// round 10
// speedup vs baseline: 1.2240x; 1.2238x over previous
#include <cuda_runtime.h>
#include <cuda_bf16.h>
#include <stdint.h>

// Problem constants (fixed by the dataset)
#define NMAX 100000
#define EMAX 1600000
#define DIN  256
#define DOUT 128

// ---------------- scratch (static device allocations; no runtime alloc) ----
static __device__ int    d_deg[NMAX];
static __device__ float  d_dinv[NMAX];
static __device__ int    d_rowstart[NMAX];
static __device__ int    d_cursor[NMAX];
static __device__ int    d_csr[EMAX];
static __device__ float4 d_g4[(size_t)NMAX * DOUT / 4];   // 51.2 MB
static __device__ int    d_tmpscan[NMAX];
static __device__ int    d_bsum[512];
static __device__ int    d_bsumscan[512];
static __device__ int    d_is64;
// W transposed + split: Wt[n][k], bf16 hi and lo residual
static __device__ __nv_bfloat16 d_wth[DOUT * DIN];
static __device__ __nv_bfloat16 d_wtl[DOUT * DIN];

// ---------------- dtype probe (parallel, graph-capturable) -----------------
__global__ void k_detect(const long long* __restrict__ p) {
    __shared__ int anybad;
    int t = threadIdx.x;
    if (t == 0) anybad = 0;
    __syncthreads();
    long long v = p[t];
    int bad = (v < 0 || v >= NMAX) ? 1 : 0;
    unsigned m = __ballot_sync(0xffffffffu, bad);
    if ((t & 31) == 0 && m) atomicOr(&anybad, 1);
    __syncthreads();
    if (t == 0) d_is64 = anybad ? 0 : 1;
}

__device__ __forceinline__ int load_idx(const void* __restrict__ ei,
                                        size_t pos) {
    if (d_is64) return (int)((const long long*)ei)[pos];
    return ((const int*)ei)[pos];
}

// ---------------- small kernels -------------------------------------------
__global__ void k_init(int n) {
    int i = blockIdx.x * blockDim.x + threadIdx.x;
    if (i < n) d_deg[i] = 0;
}

__global__ void k_degree(const void* __restrict__ ei, int e) {
    int i = blockIdx.x * blockDim.x + threadIdx.x;
    if (i < e) {
        int d = load_idx(ei, (size_t)e + i);
        atomicAdd(&d_deg[d], 1);
    }
}

__global__ void k_dinv(int n) {
    int i = blockIdx.x * blockDim.x + threadIdx.x;
    if (i < n) d_dinv[i] = rsqrtf((float)(d_deg[i] + 1));
}

__global__ void k_scan1(int n) {
    __shared__ int s[512];
    int t = threadIdx.x;
    int i = blockIdx.x * 512 + t;
    s[t] = (i < n) ? d_deg[i] : 0;
    __syncthreads();
    #pragma unroll
    for (int off = 1; off < 512; off <<= 1) {
        int add = (t >= off) ? s[t - off] : 0;
        __syncthreads();
        s[t] += add;
        __syncthreads();
    }
    if (i < n) d_tmpscan[i] = s[t];
    if (t == 511) d_bsum[blockIdx.x] = s[511];
}

__global__ void k_scan2(int nb) {
    __shared__ int s[256];
    int t = threadIdx.x;
    s[t] = (t < nb) ? d_bsum[t] : 0;
    __syncthreads();
    #pragma unroll
    for (int off = 1; off < 256; off <<= 1) {
        int add = (t >= off) ? s[t - off] : 0;
        __syncthreads();
        s[t] += add;
        __syncthreads();
    }
    if (t < nb) d_bsumscan[t] = s[t];
}

__global__ void k_scan3(int n) {
    int i = blockIdx.x * blockDim.x + threadIdx.x;
    if (i < n) {
        int b = i >> 9;
        int base = b ? d_bsumscan[b - 1] : 0;
        int rs = base + d_tmpscan[i] - d_deg[i];
        d_rowstart[i] = rs;
        d_cursor[i] = rs;
    }
}

__global__ void k_fill(const void* __restrict__ ei, int e) {
    int i = blockIdx.x * blockDim.x + threadIdx.x;
    if (i < e) {
        int s = load_idx(ei, (size_t)i);
        int d = load_idx(ei, (size_t)e + i);
        int p = atomicAdd(&d_cursor[d], 1);
        d_csr[p] = s;
    }
}

// ---------------- W split+transpose: Wt_h/l[n][k] = split(W[k][n]) --------
__global__ void k_wsplit(const float* __restrict__ W) {
    int i = blockIdx.x * blockDim.x + threadIdx.x;  // over DIN*DOUT
    if (i < DIN * DOUT) {
        int k = i / DOUT, ncol = i % DOUT;
        float v = W[i];
        __nv_bfloat16 h = __float2bfloat16(v);
        float r = v - __bfloat162float(h);
        d_wth[ncol * DIN + k] = h;
        d_wtl[ncol * DIN + k] = __float2bfloat16(r);
    }
}

// ============================================================================
// Tensor-core GEMM via mma.sync (base-target HMMA, works on compute_103):
//   g[r,:] = dinv[r] * (x[r,:] @ W)
// bf16 hi/lo compensated: D += xh@Wh + xl@Wh + xh@Wl, fp32 accumulators.
// Block: 128 rows x 128 cols, 8 warps (2m x 4n), warp tile 64x32.
// K = 256 in 2 smem chunks of 128. Row stride padded to 272B (conflict-free).
// ============================================================================
#define ASTRIDE 272                      // bytes per 128-bf16 row (+8 pad)
#define SM_AH 0
#define SM_AL (SM_AH + 128 * ASTRIDE)    // 34816
#define SM_BH (SM_AL + 128 * ASTRIDE)
#define SM_BL (SM_BH + 128 * ASTRIDE)
#define SM_GTOT (SM_BL + 128 * ASTRIDE)  // 139264 bytes

__device__ __forceinline__ uint32_t pack_bf16x2(float lo, float hi) {
    uint32_t u;  // first operand -> upper half
    asm("cvt.rn.bf16x2.f32 %0, %1, %2;" : "=r"(u) : "f"(hi), "f"(lo));
    return u;
}

__device__ __forceinline__ void ldsm_x4(uint32_t* r, uint32_t a) {
    asm volatile("ldmatrix.sync.aligned.m8n8.x4.shared.b16 {%0,%1,%2,%3}, [%4];"
                 : "=r"(r[0]), "=r"(r[1]), "=r"(r[2]), "=r"(r[3]) : "r"(a));
}
__device__ __forceinline__ void ldsm_x2(uint32_t* r, uint32_t a) {
    asm volatile("ldmatrix.sync.aligned.m8n8.x2.shared.b16 {%0,%1}, [%2];"
                 : "=r"(r[0]), "=r"(r[1]) : "r"(a));
}
__device__ __forceinline__ void mma_bf16(float* c, const uint32_t* a,
                                         const uint32_t* b) {
    asm volatile(
        "mma.sync.aligned.m16n8k16.row.col.f32.bf16.bf16.f32 "
        "{%0,%1,%2,%3}, {%4,%5,%6,%7}, {%8,%9}, {%0,%1,%2,%3};"
        : "+f"(c[0]), "+f"(c[1]), "+f"(c[2]), "+f"(c[3])
        : "r"(a[0]), "r"(a[1]), "r"(a[2]), "r"(a[3]), "r"(b[0]), "r"(b[1]));
}

__global__ __launch_bounds__(256, 1) void k_gemm_mma(const float* __restrict__ x,
                                                     int n) {
    extern __shared__ char smem[];
    const uint32_t sbase = (uint32_t)__cvta_generic_to_shared(smem);
    const int tid = threadIdx.x;
    const int wid = tid >> 5;
    const int lane = tid & 31;
    const int row0 = blockIdx.x * 128;

    const int warp_m = wid >> 2;           // 0..1 -> 64 rows each
    const int warp_n = wid & 3;            // 0..3 -> 32 cols each
    const int m0w = warp_m * 64;
    const int n0w = warp_n * 32;

    float c[4][4][4];                      // [m-frag][n-frag][c0..c3]
    #pragma unroll
    for (int i = 0; i < 4; i++)
        #pragma unroll
        for (int j = 0; j < 4; j++)
            #pragma unroll
            for (int q = 0; q < 4; q++) c[i][j][q] = 0.f;

    // ldmatrix per-thread source coordinates
    const int a_row = lane & 15;                 // + m-frag base
    const int a_kc  = (lane >> 4) << 3;          // 0 or 8
    const int b_row = lane & 7;                  // + n-frag base
    const int b_kc  = ((lane >> 3) & 1) << 3;    // 0 or 8 (lanes>=16 replicate)

    for (int ch = 0; ch < 2; ch++) {
        const int kt = ch * 128;
        // ---- fill A chunk (x -> bf16 hi/lo), rows padded to ASTRIDE ----
        for (int it = tid; it < 2048; it += 256) {
            int row = it >> 4;
            int col = (it & 15) << 3;            // 8 bf16 elems
            int gr = row0 + row;
            float4 v0 = make_float4(0.f, 0.f, 0.f, 0.f), v1 = v0;
            if (gr < n) {
                const float* p = x + (size_t)gr * DIN + kt + col;
                v0 = *(const float4*)p;
                v1 = *(const float4*)(p + 4);
            }
            float e[8] = {v0.x, v0.y, v0.z, v0.w, v1.x, v1.y, v1.z, v1.w};
            uint32_t hu[4], lu[4];
            #pragma unroll
            for (int q = 0; q < 4; q++) {
                hu[q] = pack_bf16x2(e[2 * q], e[2 * q + 1]);
                float f0h = __uint_as_float(hu[q] << 16);
                float f1h = __uint_as_float(hu[q] & 0xffff0000u);
                lu[q] = pack_bf16x2(e[2 * q] - f0h, e[2 * q + 1] - f1h);
            }
            char* dst = smem + row * ASTRIDE + col * 2;
            *(uint4*)(dst + SM_AH) = make_uint4(hu[0], hu[1], hu[2], hu[3]);
            *(uint4*)(dst + SM_AL) = make_uint4(lu[0], lu[1], lu[2], lu[3]);
        }
        // ---- fill B chunk from pre-split Wt ----
        for (int it = tid; it < 2048; it += 256) {
            int nr = it >> 4;
            int col = (it & 15) << 3;
            char* dst = smem + nr * ASTRIDE + col * 2;
            *(uint4*)(dst + SM_BH) = *(const uint4*)(d_wth + nr * DIN + kt + col);
            *(uint4*)(dst + SM_BL) = *(const uint4*)(d_wtl + nr * DIN + kt + col);
        }
        __syncthreads();

        // ---- 8 k-steps of 16 ----
        #pragma unroll
        for (int k0 = 0; k0 < 128; k0 += 16) {
            uint32_t ah[4][4], al[4][4], bh[4][2], bl[4][2];
            #pragma unroll
            for (int mi = 0; mi < 4; mi++) {
                uint32_t off = (uint32_t)((m0w + mi * 16 + a_row) * ASTRIDE
                                          + (k0 + a_kc) * 2);
                ldsm_x4(ah[mi], sbase + SM_AH + off);
                ldsm_x4(al[mi], sbase + SM_AL + off);
            }
            #pragma unroll
            for (int ni = 0; ni < 4; ni++) {
                uint32_t off = (uint32_t)((n0w + ni * 8 + b_row) * ASTRIDE
                                          + (k0 + b_kc) * 2);
                ldsm_x2(bh[ni], sbase + SM_BH + off);
                ldsm_x2(bl[ni], sbase + SM_BL + off);
            }
            #pragma unroll
            for (int mi = 0; mi < 4; mi++)
                #pragma unroll
                for (int ni = 0; ni < 4; ni++) {
                    mma_bf16(c[mi][ni], ah[mi], bh[ni]);
                    mma_bf16(c[mi][ni], al[mi], bh[ni]);
                    mma_bf16(c[mi][ni], ah[mi], bl[ni]);
                }
        }
        __syncthreads();
    }

    // ---- epilogue: scale rows by dinv, store to d_g ----
    const int g = lane >> 2;
    const int t2 = (lane & 3) << 1;
    float* gout = (float*)d_g4;
    #pragma unroll
    for (int mi = 0; mi < 4; mi++) {
        int r0 = row0 + m0w + mi * 16 + g;
        int r1 = r0 + 8;
        float dv0 = (r0 < n) ? d_dinv[r0] : 0.f;
        float dv1 = (r1 < n) ? d_dinv[r1] : 0.f;
        #pragma unroll
        for (int ni = 0; ni < 4; ni++) {
            int col = n0w + ni * 8 + t2;
            if (r0 < n) {
                float2 o = make_float2(c[mi][ni][0] * dv0, c[mi][ni][1] * dv0);
                *(float2*)(gout + (size_t)r0 * DOUT + col) = o;
            }
            if (r1 < n) {
                float2 o = make_float2(c[mi][ni][2] * dv1, c[mi][ni][3] * dv1);
                *(float2*)(gout + (size_t)r1 * DOUT + col) = o;
            }
        }
    }
}

// ---------------- Aggregate: out[d] = relu(dinv[d]*(g[d] + sum g[src]) + b)
__global__ __launch_bounds__(256) void k_agg(const float* __restrict__ bias,
                                             float* __restrict__ out, int n) {
    int gwarp = (blockIdx.x * blockDim.x + threadIdx.x) >> 5;
    int lane = threadIdx.x & 31;
    if (gwarp >= n) return;

    float4 acc = d_g4[(size_t)gwarp * 32 + lane];   // self-loop term

    int start = d_rowstart[gwarp];
    int cnt = d_deg[gwarp];
    int e = start, end = start + cnt;

    for (; e + 4 <= end; e += 4) {
        int s0 = d_csr[e + 0];
        int s1 = d_csr[e + 1];
        int s2 = d_csr[e + 2];
        int s3 = d_csr[e + 3];
        float4 v0 = d_g4[(size_t)s0 * 32 + lane];
        float4 v1 = d_g4[(size_t)s1 * 32 + lane];
        float4 v2 = d_g4[(size_t)s2 * 32 + lane];
        float4 v3 = d_g4[(size_t)s3 * 32 + lane];
        acc.x += (v0.x + v1.x) + (v2.x + v3.x);
        acc.y += (v0.y + v1.y) + (v2.y + v3.y);
        acc.z += (v0.z + v1.z) + (v2.z + v3.z);
        acc.w += (v0.w + v1.w) + (v2.w + v3.w);
    }
    for (; e < end; e++) {
        int s = d_csr[e];
        float4 v = d_g4[(size_t)s * 32 + lane];
        acc.x += v.x; acc.y += v.y; acc.z += v.z; acc.w += v.w;
    }

    float dv = d_dinv[gwarp];
    float4 bv = ((const float4*)bias)[lane];
    float4 o;
    o.x = fmaxf(fmaf(dv, acc.x, bv.x), 0.f);
    o.y = fmaxf(fmaf(dv, acc.y, bv.y), 0.f);
    o.z = fmaxf(fmaf(dv, acc.z, bv.z), 0.f);
    o.w = fmaxf(fmaf(dv, acc.w, bv.w), 0.f);
    ((float4*)out)[(size_t)gwarp * 32 + lane] = o;
}

// ---------------- launch ---------------------------------------------------
extern "C" void kernel_launch(void* const* d_in, const int* in_sizes, int n_in,
                              void* d_out, int out_size) {
    const float* x = (const float*)d_in[0];
    const void*  ei = (const void*)d_in[1];
    const float* W = (const float*)d_in[2];
    const float* bias = (const float*)d_in[3];
    float* out = (float*)d_out;

    int n = in_sizes[0] / DIN;    // 100000
    int e = in_sizes[1] / 2;      // 1600000
    int nb1 = (n + 511) / 512;

    static int smem_set = 0;
    if (!smem_set) {
        cudaFuncSetAttribute(k_gemm_mma,
                             cudaFuncAttributeMaxDynamicSharedMemorySize,
                             SM_GTOT);
        smem_set = 1;
    }

    k_detect<<<1, 256>>>((const long long*)ei);
    k_init<<<(n + 255) / 256, 256>>>(n);
    k_degree<<<(e + 255) / 256, 256>>>(ei, e);
    k_dinv<<<(n + 255) / 256, 256>>>(n);
    k_scan1<<<nb1, 512>>>(n);
    k_scan2<<<1, 256>>>(nb1);
    k_scan3<<<(n + 255) / 256, 256>>>(n);
    k_fill<<<(e + 255) / 256, 256>>>(ei, e);
    k_wsplit<<<(DIN * DOUT + 255) / 256, 256>>>(W);
    k_gemm_mma<<<(n + 127) / 128, 256, SM_GTOT>>>(x, n);
    k_agg<<<(n + 7) / 8, 256>>>(bias, out, n);
}